// round 11
// baseline (speedup 1.0000x reference)
#include <cuda_runtime.h>
#include <cuda_bf16.h>
#include <cuda_fp16.h>
#include <math.h>
#include <stdint.h>

#define BB 2
#define SS 2048
#define DD 1024
#define HH 16
#define DHD 64
#define RR 256
#define NEXP 16
#define NKK 4096
#define TK 8
#define TT (BB*SS)

// ---------------- scratch (device globals; no allocation allowed) -------------
__device__ float g_nx [BB*SS*DD];
__device__ float g_nx2[BB*SS*DD];
__device__ float g_w  [4*BB*NEXP];
__device__ float g_wm [BB*NEXP];
__device__ float g_sc [BB*DD*RR];
__device__ float g_mc [BB*DD*RR];
__device__ float g_h  [BB*SS*RR];
__device__ float g_qm [BB*SS*RR];
__device__ float g_eq [BB*RR*DD];
__device__ float g_ek [BB*RR*DD];
__device__ float g_ev [BB*RR*DD];
__device__ float g_q  [BB*SS*DD];
__device__ float g_k  [BB*SS*DD];
__device__ float g_v  [BB*SS*DD];
__device__ float g_ao [BB*SS*DD];
__device__ float g_x1 [BB*SS*DD];
__device__ float g_ms [(size_t)BB*SS*NKK];   // used as fp16 (half capacity)
__device__ float g_lgp[(size_t)TT*64];       // compact pooled logits

// ---------------- utility ------------------------------------------------------
// zero h, qm (1M floats each), lgp (256K), w/wm. grid 1024 x 256.
__global__ void __launch_bounds__(256) zeroall_kernel(float4* h4, float4* q4,
                                                      float4* lgp4,
                                                      float* w, float* wm) {
    int i = blockIdx.x * 256 + threadIdx.x;
    float4 z = make_float4(0.f, 0.f, 0.f, 0.f);
    h4[i] = z; q4[i] = z;
    if (blockIdx.x < 256) lgp4[i] = z;
    if (blockIdx.x == 0) {
        if (threadIdx.x < 128) w[threadIdx.x] = 0.f;
        else if (threadIdx.x < 160) wm[threadIdx.x - 128] = 0.f;
    }
}

__device__ __forceinline__ float tf32r(float x) {
    uint32_t u;
    asm("cvt.rna.tf32.f32 %0, %1;" : "=r"(u) : "f"(x));
    return __uint_as_float(u);
}

__device__ __forceinline__ void sts4_tf32(float* p, float4 v) {
    float4 o;
    o.x = tf32r(v.x); o.y = tf32r(v.y); o.z = tf32r(v.z); o.w = tf32r(v.w);
    *(float4*)p = o;
}

__device__ __forceinline__ void mma8(float* c, const float* a, const float* b) {
    uint32_t A0 = __float_as_uint(a[0]), A1 = __float_as_uint(a[1]);
    uint32_t A2 = __float_as_uint(a[2]), A3 = __float_as_uint(a[3]);
    uint32_t B0 = __float_as_uint(b[0]), B1 = __float_as_uint(b[1]);
    asm volatile(
        "mma.sync.aligned.m16n8k8.row.col.f32.tf32.tf32.f32 "
        "{%0,%1,%2,%3}, {%4,%5,%6,%7}, {%8,%9}, {%0,%1,%2,%3};\n"
        : "+f"(c[0]), "+f"(c[1]), "+f"(c[2]), "+f"(c[3])
        : "r"(A0), "r"(A1), "r"(A2), "r"(A3), "r"(B0), "r"(B1));
}

__device__ __forceinline__ void mma16(float* c, const uint32_t* a, const uint32_t* b) {
    asm volatile(
        "mma.sync.aligned.m16n8k16.row.col.f32.f16.f16.f32 "
        "{%0,%1,%2,%3}, {%4,%5,%6,%7}, {%8,%9}, {%0,%1,%2,%3};\n"
        : "+f"(c[0]), "+f"(c[1]), "+f"(c[2]), "+f"(c[3])
        : "r"(a[0]), "r"(a[1]), "r"(a[2]), "r"(a[3]), "r"(b[0]), "r"(b[1]));
}

// ---------------- LayerNorm: one block per row, 256 threads --------------------
__global__ void __launch_bounds__(256) ln_kernel(const float* __restrict__ x,
                                                 const float* __restrict__ g,
                                                 const float* __restrict__ b,
                                                 float* __restrict__ out) {
    int row = blockIdx.x;
    const float4* xr = (const float4*)(x + (size_t)row * DD);
    float4 t = xr[threadIdx.x];
    float s  = t.x + t.y + t.z + t.w;
    float sq = t.x*t.x + t.y*t.y + t.z*t.z + t.w*t.w;
    __shared__ float rs[8], rq[8];
    for (int o = 16; o; o >>= 1) {
        s  += __shfl_down_sync(0xffffffffu, s,  o);
        sq += __shfl_down_sync(0xffffffffu, sq, o);
    }
    int wid = threadIdx.x >> 5, lane = threadIdx.x & 31;
    if (lane == 0) { rs[wid] = s; rq[wid] = sq; }
    __syncthreads();
    if (threadIdx.x == 0) {
        float a = 0.f, c = 0.f;
        for (int i = 0; i < 8; i++) { a += rs[i]; c += rq[i]; }
        rs[0] = a; rq[0] = c;
    }
    __syncthreads();
    float mean = rs[0] * (1.f / DD);
    float var  = rq[0] * (1.f / DD) - mean * mean;
    float rstd = rsqrtf(var + 1e-5f);
    float4 gg = ((const float4*)g)[threadIdx.x];
    float4 bb = ((const float4*)b)[threadIdx.x];
    float4 o4;
    o4.x = (t.x - mean) * rstd * gg.x + bb.x;
    o4.y = (t.y - mean) * rstd * gg.y + bb.y;
    o4.z = (t.z - mean) * rstd * gg.z + bb.z;
    o4.w = (t.w - mean) * rstd * gg.w + bb.w;
    ((float4*)(out + (size_t)row * DD))[threadIdx.x] = o4;
}

// ---------------- routing v6: 4 tok x 4 exp, 2 chunks/block, atomic pool -------
// grid (TT/16, 4). Block accumulates chunks y and y+4, atomicAdds into compact
// lgp[token][64] (pre-zeroed; pool4 clears after read for next pass/replay).
__global__ void __launch_bounds__(256) route6_kernel(
    const float* __restrict__ nx,
    const float* __restrict__ W0, const float* __restrict__ W1,
    const float* __restrict__ W2, const float* __restrict__ W3,
    int nE, float* __restrict__ lgp) {
    __shared__ float xs[16 * 132];
    __shared__ float ws[64 * 132];   // reused as partials [4][16][68]
    int tid = threadIdx.x;
    int tok0 = blockIdx.x * 16;
    int dq = tid >> 6, tg = (tid >> 4) & 3, eg = tid & 15;
    const float* Ws[4] = {W0, W1, W2, W3};
    bool em[4];
#pragma unroll
    for (int i = 0; i < 4; i++) em[i] = (eg + i * 16) < nE;
    float a[4][4];
#pragma unroll
    for (int j = 0; j < 4; j++)
#pragma unroll
        for (int i = 0; i < 4; i++) a[j][i] = 0.f;

#pragma unroll
    for (int ci = 0; ci < 2; ci++) {
        int c = blockIdx.y + ci * 4;
        __syncthreads();
#pragma unroll
        for (int i = 0; i < 2; i++) {
            int f = tid + 256 * i;
            int tt = f >> 5, d4 = f & 31;
            *(float4*)&xs[tt * 132 + d4 * 4] =
                *(const float4*)(nx + (size_t)(tok0 + tt) * DD + c * 128 + d4 * 4);
        }
#pragma unroll
        for (int i = 0; i < 8; i++) {
            int f = tid + 256 * i;
            if (f < nE * 32) {
                int e = f >> 5, d4 = f & 31;
                const float* src = Ws[e >> 4] + (size_t)(e & 15) * DD + c * 128 + d4 * 4;
                *(float4*)&ws[e * 132 + d4 * 4] = *(const float4*)src;
            }
        }
        __syncthreads();
#pragma unroll
        for (int d4 = dq * 8; d4 < dq * 8 + 8; d4++) {
            float4 xv[4], wv[4];
#pragma unroll
            for (int j = 0; j < 4; j++)
                xv[j] = *(float4*)&xs[(tg * 4 + j) * 132 + d4 * 4];
#pragma unroll
            for (int i = 0; i < 4; i++)
                wv[i] = em[i] ? *(float4*)&ws[(eg + i * 16) * 132 + d4 * 4]
                              : make_float4(0.f, 0.f, 0.f, 0.f);
#pragma unroll
            for (int j = 0; j < 4; j++)
#pragma unroll
                for (int i = 0; i < 4; i++)
                    a[j][i] += xv[j].x * wv[i].x + xv[j].y * wv[i].y +
                               xv[j].z * wv[i].z + xv[j].w * wv[i].w;
        }
    }
    __syncthreads();
    float* part = ws;     // [dq][t(16)][68]
#pragma unroll
    for (int j = 0; j < 4; j++)
#pragma unroll
        for (int i = 0; i < 4; i++)
            part[dq * 1088 + (tg * 4 + j) * 68 + eg + i * 16] = a[j][i];
    __syncthreads();
    {
        int t = tid >> 4, e0 = (tid * 4) & 63;
        float4 s = make_float4(0.f, 0.f, 0.f, 0.f);
#pragma unroll
        for (int d = 0; d < 4; d++) {
            float4 p = *(float4*)&part[d * 1088 + t * 68 + e0];
            s.x += p.x; s.y += p.y; s.z += p.z; s.w += p.w;
        }
        float* dst = &lgp[(size_t)(tok0 + t) * 64 + e0];
        atomicAdd(dst + 0, s.x);
        atomicAdd(dst + 1, s.y);
        atomicAdd(dst + 2, s.z);
        atomicAdd(dst + 3, s.w);
    }
}

// pool compact logits: softmax in 16-expert segments, pooled accumulate.
// Clears lgp after reading (ready for next routing pass / graph replay).
__global__ void __launch_bounds__(256) pool4_kernel(
    float* __restrict__ lgp, const float* __restrict__ imp,
    int nW, float* __restrict__ wacc) {
    int tid = threadIdx.x;
    int t = tid >> 6, e = tid & 63;
    int tok = blockIdx.x * 4 + t;
    size_t idx = (size_t)tok * 64 + e;
    float l = lgp[idx];
    lgp[idx] = 0.f;
    float mx = l;
#pragma unroll
    for (int o = 1; o < 16; o <<= 1)
        mx = fmaxf(mx, __shfl_xor_sync(0xffffffffu, mx, o));
    float ev = __expf(l - mx);
    float s = ev;
#pragma unroll
    for (int o = 1; o < 16; o <<= 1)
        s += __shfl_xor_sync(0xffffffffu, s, o);
    if (e < nW * NEXP) {
        int r = e >> 4, n = e & 15, b = tok / SS;
        atomicAdd(&wacc[(r * BB + b) * NEXP + n], imp[tok] * ev / s);
    }
}

__global__ void norm_kernel(float* w, int cnt) {
    int i = threadIdx.x;
    if (i < cnt) {
        float* p = w + i * NEXP;
        float s = 0.f;
        for (int n = 0; n < NEXP; n++) s += p[n];
        float inv = 1.f / (s + 1e-8f);
        for (int n = 0; n < NEXP; n++) p[n] *= inv;
    }
}

// ---------------- pool mixes: both batches per thread (pool read once) ---------
__global__ void __launch_bounds__(256) mixfused2_kernel(
    const float* __restrict__ w, const float* __restrict__ CN,
    const float* __restrict__ EP, float* __restrict__ sc,
    float* __restrict__ eq, float* __restrict__ ek, float* __restrict__ ev) {
    const size_t X = (size_t)DD * RR;
    if (blockIdx.x < 1024) {
        size_t r = (size_t)blockIdx.x * 256 + threadIdx.x;
        float a0 = 0.f, a1 = 0.f;
#pragma unroll
        for (int n = 0; n < NEXP; n++) {
            float p = CN[(size_t)n * X + r];
            a0 += w[n] * p;
            a1 += w[16 + n] * p;
        }
        sc[r] = a0; sc[X + r] = a1;
    } else {
        size_t r = (size_t)(blockIdx.x - 1024) * 256 + threadIdx.x;
        float q0 = 0.f, q1 = 0.f, k0 = 0.f, k1 = 0.f, v0 = 0.f, v1 = 0.f;
#pragma unroll
        for (int n = 0; n < NEXP; n++) {
            float p = EP[(size_t)n * X + r];
            q0 += w[32 + n] * p; q1 += w[48 + n] * p;
            k0 += w[64 + n] * p; k1 += w[80 + n] * p;
            v0 += w[96 + n] * p; v1 += w[112 + n] * p;
        }
        eq[r] = q0; eq[X + r] = q1;
        ek[r] = k0; ek[X + r] = k1;
        ev[r] = v0; ev[X + r] = v1;
    }
}

__global__ void __launch_bounds__(256) mix2_kernel(
    const float* __restrict__ wm, const float* __restrict__ CN,
    float* __restrict__ mc) {
    const size_t X = (size_t)DD * RR;
    size_t r = (size_t)blockIdx.x * 256 + threadIdx.x;
    float a0 = 0.f, a1 = 0.f;
#pragma unroll
    for (int n = 0; n < NEXP; n++) {
        float p = CN[(size_t)n * X + r];
        a0 += wm[n] * p;
        a1 += wm[16 + n] * p;
    }
    mc[r] = a0; mc[X + r] = a1;
}

// ---------------- tf32 tensor-core GEMM body (NN path) -------------------------
template<bool TRANSB, bool RES, bool ATOM>
__device__ __forceinline__ void tgemm_body(
    const float* __restrict__ A, const float* __restrict__ B,
    const float* __restrict__ resp, float* __restrict__ Cf,
    int N, int K, int lda, int ldb, float alpha) {
    const int n0 = blockIdx.x * 128, m0 = blockIdx.y * 128;
    __shared__ float As[128 * 20];
    __shared__ float Bs[2560];
    int tid = threadIdx.x;
    int lane = tid & 31, w = tid >> 5;
    int wm = (w & 1) * 64, wn = (w >> 1) * 32;
    int lq = lane >> 2, lr = lane & 3;

    int rowA = tid >> 2, c4A = (tid & 3) * 4;
    const float* gA = A + (size_t)(m0 + rowA) * lda + c4A;
    float* sAp = &As[rowA * 20 + c4A];
    const float* gB;
    float* sBp;
    int gBstep, gBoff2, sBoff2;
    if (!TRANSB) {
        int rB = tid >> 5, cB = (tid & 31) * 4;
        gB = B + (size_t)rB * ldb + n0 + cB;
        sBp = &Bs[rB * 136 + cB];
        gBstep = 16 * ldb; gBoff2 = 8 * ldb; sBoff2 = 8 * 136;
    } else {
        int nB = tid >> 2, c4B = (tid & 3) * 4;
        gB = B + (size_t)(n0 + nB) * ldb + c4B;
        sBp = &Bs[nB * 20 + c4B];
        gBstep = 16; gBoff2 = 64 * ldb; sBoff2 = 64 * 20;
    }

    float acc[4][4][4];
#pragma unroll
    for (int mt = 0; mt < 4; mt++)
#pragma unroll
        for (int nt = 0; nt < 4; nt++)
#pragma unroll
            for (int i = 0; i < 4; i++) acc[mt][nt][i] = 0.f;

    float4 pa0 = *(const float4*)gA;
    float4 pa1 = *(const float4*)(gA + (size_t)64 * lda);
    float4 pb0 = *(const float4*)gB;
    float4 pb1 = *(const float4*)(gB + gBoff2);

    for (int kt = 0; kt < K; kt += 16) {
        sts4_tf32(sAp, pa0);
        sts4_tf32(sAp + 64 * 20, pa1);
        sts4_tf32(sBp, pb0);
        sts4_tf32(sBp + sBoff2, pb1);
        __syncthreads();
        if (kt + 16 < K) {
            gA += 16;
            pa0 = *(const float4*)gA;
            pa1 = *(const float4*)(gA + (size_t)64 * lda);
            gB += gBstep;
            pb0 = *(const float4*)gB;
            pb1 = *(const float4*)(gB + gBoff2);
        }
#pragma unroll
        for (int ks = 0; ks < 16; ks += 8) {
            float af[4][4], bf[4][2];
#pragma unroll
            for (int mt = 0; mt < 4; mt++) {
                int r = wm + mt * 16 + lq;
                af[mt][0] = As[r * 20 + ks + lr];
                af[mt][1] = As[(r + 8) * 20 + ks + lr];
                af[mt][2] = As[r * 20 + ks + lr + 4];
                af[mt][3] = As[(r + 8) * 20 + ks + lr + 4];
            }
#pragma unroll
            for (int nt = 0; nt < 4; nt++) {
                int cc = wn + nt * 8 + lq;
                if (!TRANSB) {
                    bf[nt][0] = Bs[(ks + lr) * 136 + cc];
                    bf[nt][1] = Bs[(ks + 4 + lr) * 136 + cc];
                } else {
                    bf[nt][0] = Bs[cc * 20 + ks + lr];
                    bf[nt][1] = Bs[cc * 20 + ks + 4 + lr];
                }
            }
#pragma unroll
            for (int mt = 0; mt < 4; mt++)
#pragma unroll
                for (int nt = 0; nt < 4; nt++)
                    mma8(acc[mt][nt], af[mt], bf[nt]);
        }
        __syncthreads();
    }
#pragma unroll
    for (int mt = 0; mt < 4; mt++) {
        int r = m0 + wm + mt * 16 + lq;
#pragma unroll
        for (int nt = 0; nt < 4; nt++) {
            int cc = n0 + wn + nt * 8 + 2 * lr;
            float2 v0 = make_float2(alpha * acc[mt][nt][0], alpha * acc[mt][nt][1]);
            float2 v1 = make_float2(alpha * acc[mt][nt][2], alpha * acc[mt][nt][3]);
            size_t o0 = (size_t)r * N + cc;
            size_t o1 = (size_t)(r + 8) * N + cc;
            if (ATOM) {
                atomicAdd(Cf + o0, v0.x); atomicAdd(Cf + o0 + 1, v0.y);
                atomicAdd(Cf + o1, v1.x); atomicAdd(Cf + o1 + 1, v1.y);
            } else {
                if (RES) {
                    float2 r0 = *(const float2*)(resp + o0);
                    float2 r1 = *(const float2*)(resp + o1);
                    v0.x += r0.x; v0.y += r0.y;
                    v1.x += r1.x; v1.y += r1.y;
                }
                *(float2*)(Cf + o0) = v0;
                *(float2*)(Cf + o1) = v1;
            }
        }
    }
}

// split-K (x2) NN GEMM with atomic epilogue. grid.z = b*2 + ks.
__global__ void __launch_bounds__(256, 2) splitk_kernel(
    const float* __restrict__ A, const float* __restrict__ B,
    float* __restrict__ C, int N, int Kh, int lda, int ldb,
    long sA, long sB, long sC) {
    int z = blockIdx.z;
    int b = z >> 1, ks = z & 1;
    A += (size_t)b * sA + (size_t)ks * Kh;
    B += (size_t)b * sB + (size_t)ks * Kh * ldb;
    C += (size_t)b * sC;
    tgemm_body<false, false, true>(A, B, nullptr, C, N, Kh, lda, ldb, 1.f);
}

// merged Q/K/V projection: grid.z = 6 (which = z>>1, b = z&1)
__global__ void __launch_bounds__(256, 2) qkv_kernel(
    const float* __restrict__ h,
    const float* __restrict__ eq, const float* __restrict__ ek,
    const float* __restrict__ ev,
    float* __restrict__ q, float* __restrict__ k, float* __restrict__ v) {
    int z = blockIdx.z;
    int b = z & 1, which = z >> 1;
    const float* B = (which == 0 ? eq : which == 1 ? ek : ev) + (size_t)b * RR * DD;
    float* C = (which == 0 ? q : which == 1 ? k : v) + (size_t)b * SS * DD;
    const float* A = h + (size_t)b * SS * RR;
    tgemm_body<false, false, false>(A, B, nullptr, C, DD, RR, RR, DD, 1.f);
}

// ---------------- fp16 m16n8k16 NT GEMM: 128x128 tile, BK=32 -------------------
// A [M,K] fp32, B [N,K] fp32 (both k-contiguous), converted to fp16 at staging.
// fp16 eps == tf32 eps (10-bit mantissa) -> accuracy-neutral vs tf32.
template<bool RES, bool OUTHALF>
__global__ void __launch_bounds__(256, 2) hgemm_nt_kernel(
    const float* __restrict__ A, const float* __restrict__ B,
    const float* __restrict__ resp, void* __restrict__ Cv,
    int N, int K, int lda, int ldb, float alpha,
    long sA, long sB, long sC, long sR) {
    A += (size_t)blockIdx.z * sA;
    B += (size_t)blockIdx.z * sB;
    __half* Ch = (__half*)Cv;
    float* Cf = (float*)Cv;
    if (OUTHALF) Ch += (size_t)blockIdx.z * sC;
    else         Cf += (size_t)blockIdx.z * sC;
    if (RES) resp += (size_t)blockIdx.z * sR;
    const int n0 = blockIdx.x * 128, m0 = blockIdx.y * 128;
    __shared__ uint32_t AsW[128 * 20];   // [row][k-pairs], 16 data + 4 pad words
    __shared__ uint32_t BsW[128 * 20];
    int tid = threadIdx.x, lane = tid & 31, w = tid >> 5;
    int wm = (w & 1) * 64, wn = (w >> 1) * 32;
    int lq = lane >> 2, lr = lane & 3;
    int row = tid >> 3, c4 = tid & 7;    // row 0-31, float4 index within 32 k-vals

    const float* gA = A + (size_t)(m0 + row) * lda + c4 * 4;
    const float* gB = B + (size_t)(n0 + row) * ldb + c4 * 4;
    float4 pa[4], pb[4];
#pragma unroll
    for (int i = 0; i < 4; i++) {
        pa[i] = *(const float4*)(gA + (size_t)(32 * i) * lda);
        pb[i] = *(const float4*)(gB + (size_t)(32 * i) * ldb);
    }

    float acc[4][4][4];
#pragma unroll
    for (int mt = 0; mt < 4; mt++)
#pragma unroll
        for (int nt = 0; nt < 4; nt++)
#pragma unroll
            for (int i = 0; i < 4; i++) acc[mt][nt][i] = 0.f;

    for (int kt = 0; kt < K; kt += 32) {
#pragma unroll
        for (int i = 0; i < 4; i++) {
            __half2 h0 = __floats2half2_rn(pa[i].x, pa[i].y);
            __half2 h1 = __floats2half2_rn(pa[i].z, pa[i].w);
            uint2 ua;
            ua.x = *(uint32_t*)&h0; ua.y = *(uint32_t*)&h1;
            *(uint2*)&AsW[(row + 32 * i) * 20 + c4 * 2] = ua;
            __half2 g0 = __floats2half2_rn(pb[i].x, pb[i].y);
            __half2 g1 = __floats2half2_rn(pb[i].z, pb[i].w);
            uint2 ub;
            ub.x = *(uint32_t*)&g0; ub.y = *(uint32_t*)&g1;
            *(uint2*)&BsW[(row + 32 * i) * 20 + c4 * 2] = ub;
        }
        __syncthreads();
        if (kt + 32 < K) {
            gA += 32; gB += 32;
#pragma unroll
            for (int i = 0; i < 4; i++) {
                pa[i] = *(const float4*)(gA + (size_t)(32 * i) * lda);
                pb[i] = *(const float4*)(gB + (size_t)(32 * i) * ldb);
            }
        }
#pragma unroll
        for (int ks = 0; ks < 2; ks++) {
            uint32_t af[4][4], bf[4][2];
#pragma unroll
            for (int mt = 0; mt < 4; mt++) {
                int r = wm + mt * 16 + lq;
                af[mt][0] = AsW[r * 20 + ks * 8 + lr];
                af[mt][1] = AsW[(r + 8) * 20 + ks * 8 + lr];
                af[mt][2] = AsW[r * 20 + ks * 8 + 4 + lr];
                af[mt][3] = AsW[(r + 8) * 20 + ks * 8 + 4 + lr];
            }
#pragma unroll
            for (int nt = 0; nt < 4; nt++) {
                int cc = wn + nt * 8 + lq;
                bf[nt][0] = BsW[cc * 20 + ks * 8 + lr];
                bf[nt][1] = BsW[cc * 20 + ks * 8 + 4 + lr];
            }
#pragma unroll
            for (int mt = 0; mt < 4; mt++)
#pragma unroll
                for (int nt = 0; nt < 4; nt++)
                    mma16(acc[mt][nt], af[mt], bf[nt]);
        }
        __syncthreads();
    }
#pragma unroll
    for (int mt = 0; mt < 4; mt++) {
        int r = m0 + wm + mt * 16 + lq;
#pragma unroll
        for (int nt = 0; nt < 4; nt++) {
            int cc = n0 + wn + nt * 8 + 2 * lr;
            float2 v0 = make_float2(alpha * acc[mt][nt][0], alpha * acc[mt][nt][1]);
            float2 v1 = make_float2(alpha * acc[mt][nt][2], alpha * acc[mt][nt][3]);
            size_t o0 = (size_t)r * N + cc;
            size_t o1 = (size_t)(r + 8) * N + cc;
            if (OUTHALF) {
                *(__half2*)(Ch + o0) = __floats2half2_rn(v0.x, v0.y);
                *(__half2*)(Ch + o1) = __floats2half2_rn(v1.x, v1.y);
            } else {
                if (RES) {
                    float2 r0 = *(const float2*)(resp + o0);
                    float2 r1 = *(const float2*)(resp + o1);
                    v0.x += r0.x; v0.y += r0.y;
                    v1.x += r1.x; v1.y += r1.y;
                }
                *(float2*)(Cf + o0) = v0;
                *(float2*)(Cf + o1) = v1;
            }
        }
    }
}

// ---------------- tf32 tensor-core causal flash attention ----------------------
__global__ void __launch_bounds__(256, 2) fattn_kernel(
    const float* __restrict__ Q, const float* __restrict__ K,
    const float* __restrict__ V, float* __restrict__ O) {
    int b = blockIdx.z, h = blockIdx.y;
    int q0 = (gridDim.x - 1 - blockIdx.x) * 128;
    __shared__ float Ks[64 * 68];
    __shared__ float Vs[64 * 72];
    int tid = threadIdx.x, lane = tid & 31, w = tid >> 5;
    int lq = lane >> 2, lr = lane & 3;
    int wrow = q0 + w * 16;

    float qf[8][4];
    const float* Qb = Q + ((size_t)(b * SS + wrow)) * DD + h * DHD;
#pragma unroll
    for (int ks = 0; ks < 8; ks++) {
        qf[ks][0] = tf32r(0.125f * Qb[lq * DD + ks * 8 + lr]);
        qf[ks][1] = tf32r(0.125f * Qb[(lq + 8) * DD + ks * 8 + lr]);
        qf[ks][2] = tf32r(0.125f * Qb[lq * DD + ks * 8 + lr + 4]);
        qf[ks][3] = tf32r(0.125f * Qb[(lq + 8) * DD + ks * 8 + lr + 4]);
    }
    float of[8][4];
#pragma unroll
    for (int dt = 0; dt < 8; dt++) {
        of[dt][0] = 0.f; of[dt][1] = 0.f; of[dt][2] = 0.f; of[dt][3] = 0.f;
    }
    float m0 = -1e30f, m1 = -1e30f, l0 = 0.f, l1 = 0.f;

    int ntiles = q0 / 64 + 2;
    for (int ti = 0; ti < ntiles; ti++) {
        int j0 = ti * 64;
        __syncthreads();
#pragma unroll
        for (int i = 0; i < 4; i++) {
            int f = tid + 256 * i;
            int r = f >> 4, c4 = (f & 15) * 4;
            size_t goff = ((size_t)(b * SS + j0 + r)) * DD + h * DHD + c4;
            sts4_tf32(&Ks[r * 68 + c4], *(const float4*)(K + goff));
            sts4_tf32(&Vs[r * 72 + c4], *(const float4*)(V + goff));
        }
        __syncthreads();
        if (j0 > wrow + 15) continue;

        float sc[8][4];
#pragma unroll
        for (int nt = 0; nt < 8; nt++) {
            sc[nt][0] = 0.f; sc[nt][1] = 0.f; sc[nt][2] = 0.f; sc[nt][3] = 0.f;
        }
#pragma unroll
        for (int nt = 0; nt < 8; nt++)
#pragma unroll
            for (int ks = 0; ks < 8; ks++) {
                float bf[2];
                bf[0] = Ks[(nt * 8 + lq) * 68 + ks * 8 + lr];
                bf[1] = Ks[(nt * 8 + lq) * 68 + ks * 8 + lr + 4];
                mma8(sc[nt], qf[ks], bf);
            }
        if (j0 + 63 > wrow) {
            int r0 = wrow + lq, r1 = r0 + 8;
#pragma unroll
            for (int nt = 0; nt < 8; nt++) {
                int col = j0 + nt * 8 + 2 * lr;
                if (col > r0)     sc[nt][0] = -1e30f;
                if (col + 1 > r0) sc[nt][1] = -1e30f;
                if (col > r1)     sc[nt][2] = -1e30f;
                if (col + 1 > r1) sc[nt][3] = -1e30f;
            }
        }
        float mx0 = -1e30f, mx1 = -1e30f;
#pragma unroll
        for (int nt = 0; nt < 8; nt++) {
            mx0 = fmaxf(mx0, fmaxf(sc[nt][0], sc[nt][1]));
            mx1 = fmaxf(mx1, fmaxf(sc[nt][2], sc[nt][3]));
        }
        mx0 = fmaxf(mx0, __shfl_xor_sync(0xffffffffu, mx0, 1));
        mx0 = fmaxf(mx0, __shfl_xor_sync(0xffffffffu, mx0, 2));
        mx1 = fmaxf(mx1, __shfl_xor_sync(0xffffffffu, mx1, 1));
        mx1 = fmaxf(mx1, __shfl_xor_sync(0xffffffffu, mx1, 2));
        float mn0 = fmaxf(m0, mx0), mn1 = fmaxf(m1, mx1);
        float f0 = __expf(m0 - mn0), f1 = __expf(m1 - mn1);
        m0 = mn0; m1 = mn1;
        l0 *= f0; l1 *= f1;
#pragma unroll
        for (int dt = 0; dt < 8; dt++) {
            of[dt][0] *= f0; of[dt][1] *= f0;
            of[dt][2] *= f1; of[dt][3] *= f1;
        }
        float rs0 = 0.f, rs1 = 0.f;
#pragma unroll
        for (int nt = 0; nt < 8; nt++) {
            float p0 = tf32r(__expf(sc[nt][0] - m0));
            float p1 = tf32r(__expf(sc[nt][1] - m0));
            float p2 = tf32r(__expf(sc[nt][2] - m1));
            float p3 = tf32r(__expf(sc[nt][3] - m1));
            sc[nt][0] = p0; sc[nt][1] = p1; sc[nt][2] = p2; sc[nt][3] = p3;
            rs0 += p0 + p1; rs1 += p2 + p3;
        }
        rs0 += __shfl_xor_sync(0xffffffffu, rs0, 1);
        rs0 += __shfl_xor_sync(0xffffffffu, rs0, 2);
        rs1 += __shfl_xor_sync(0xffffffffu, rs1, 1);
        rs1 += __shfl_xor_sync(0xffffffffu, rs1, 2);
        l0 += rs0; l1 += rs1;
        int srcA = (lane & ~3) | (lr >> 1);
        int srcB = srcA | 2;
        bool odd = (lr & 1) != 0;
#pragma unroll
        for (int nt = 0; nt < 8; nt++) {
            float t00 = __shfl_sync(0xffffffffu, sc[nt][0], srcA);
            float t01 = __shfl_sync(0xffffffffu, sc[nt][1], srcA);
            float t02 = __shfl_sync(0xffffffffu, sc[nt][2], srcA);
            float t03 = __shfl_sync(0xffffffffu, sc[nt][3], srcA);
            float u00 = __shfl_sync(0xffffffffu, sc[nt][0], srcB);
            float u01 = __shfl_sync(0xffffffffu, sc[nt][1], srcB);
            float u02 = __shfl_sync(0xffffffffu, sc[nt][2], srcB);
            float u03 = __shfl_sync(0xffffffffu, sc[nt][3], srcB);
            float pa[4];
            pa[0] = odd ? t01 : t00;
            pa[1] = odd ? t03 : t02;
            pa[2] = odd ? u01 : u00;
            pa[3] = odd ? u03 : u02;
#pragma unroll
            for (int dt = 0; dt < 8; dt++) {
                float bf[2];
                bf[0] = Vs[(nt * 8 + lr) * 72 + dt * 8 + lq];
                bf[1] = Vs[(nt * 8 + lr + 4) * 72 + dt * 8 + lq];
                mma8(of[dt], pa, bf);
            }
        }
    }
    float inv0 = 1.f / l0, inv1 = 1.f / l1;
    float* Ob0 = O + ((size_t)(b * SS + wrow + lq)) * DD + h * DHD;
    float* Ob1 = Ob0 + (size_t)8 * DD;
#pragma unroll
    for (int dt = 0; dt < 8; dt++) {
        *(float2*)&Ob0[dt * 8 + 2 * lr] = make_float2(of[dt][0] * inv0, of[dt][1] * inv0);
        *(float2*)&Ob1[dt * 8 + 2 * lr] = make_float2(of[dt][2] * inv1, of[dt][3] * inv1);
    }
}

// ---------------- top-8 over fp16 scores + gather + residual -------------------
__global__ void __launch_bounds__(256) topk4_kernel(const __half* __restrict__ ms,
                                                    const float* __restrict__ x1,
                                                    const float* __restrict__ KV,
                                                    float* __restrict__ out) {
    int token = blockIdx.x;
    int tid = threadIdx.x, w = tid >> 5, lane = tid & 31;
    const __half* row = ms + (size_t)token * NKK;
    float r[16];
#pragma unroll
    for (int i = 0; i < 4; i++) {
        uint2 u = *(const uint2*)(row + w * 512 + i * 128 + lane * 4);
        float2 f01 = __half22float2(*(const __half2*)&u.x);
        float2 f23 = __half22float2(*(const __half2*)&u.y);
        r[i * 4 + 0] = f01.x; r[i * 4 + 1] = f01.y;
        r[i * 4 + 2] = f23.x; r[i * 4 + 3] = f23.y;
    }
    __shared__ float cv_s[64];
    __shared__ int   ci_s[64];
    __shared__ float tv[TK];
    __shared__ int   tix[TK];
    __shared__ float w8[TK];
    uint32_t taken = 0;
    for (int k = 0; k < TK; k++) {
        float bv = -1e30f; int bi = 0;
#pragma unroll
        for (int i = 0; i < 16; i++) {
            if (!((taken >> i) & 1u) && r[i] > bv) { bv = r[i]; bi = i; }
        }
        int mygi = w * 512 + (bi >> 2) * 128 + lane * 4 + (bi & 3);
        float rv = bv; int gi = mygi;
#pragma unroll
        for (int o = 16; o; o >>= 1) {
            float ov = __shfl_xor_sync(0xffffffffu, rv, o);
            int   oi = __shfl_xor_sync(0xffffffffu, gi, o);
            if (ov > rv || (ov == rv && oi < gi)) { rv = ov; gi = oi; }
        }
        if (gi == mygi) taken |= 1u << bi;
        if (lane == 0) { cv_s[w * 8 + k] = rv; ci_s[w * 8 + k] = gi; }
    }
    __syncthreads();
    if (w == 0) {
        float c0 = cv_s[lane], c1 = cv_s[lane + 32];
        int i0 = ci_s[lane], i1 = ci_s[lane + 32];
        uint32_t tk = 0;
        for (int k = 0; k < TK; k++) {
            float bv = -1e30f; int gi = 0x7fffffff; int sel = -1;
            if (!(tk & 1u)) { bv = c0; gi = i0; sel = 0; }
            if (!(tk & 2u) && (c1 > bv || (c1 == bv && i1 < gi))) {
                bv = c1; gi = i1; sel = 1;
            }
            float rv = bv; int g = gi;
#pragma unroll
            for (int o = 16; o; o >>= 1) {
                float ov = __shfl_xor_sync(0xffffffffu, rv, o);
                int   oi = __shfl_xor_sync(0xffffffffu, g, o);
                if (ov > rv || (ov == rv && oi < g)) { rv = ov; g = oi; }
            }
            if (sel >= 0 && g == gi) tk |= (sel ? 2u : 1u);
            if (lane == 0) { tv[k] = rv; tix[k] = g; }
        }
        if (lane == 0) {
            float mx = tv[0];
            float e[TK], s = 0.f;
            for (int k = 0; k < TK; k++) { e[k] = __expf(tv[k] - mx); s += e[k]; }
            float inv = 1.f / s;
            for (int k = 0; k < TK; k++) w8[k] = e[k] * inv;
        }
    }
    __syncthreads();
    {
        float4 acc = *(const float4*)(x1 + (size_t)token * DD + tid * 4);
#pragma unroll
        for (int k = 0; k < TK; k++) {
            float4 kv = *(const float4*)(KV + (size_t)tix[k] * DD + tid * 4);
            float wk = w8[k];
            acc.x += wk * kv.x; acc.y += wk * kv.y;
            acc.z += wk * kv.z; acc.w += wk * kv.w;
        }
        *(float4*)(out + (size_t)token * DD + tid * 4) = acc;
    }
}

// ---------------- driver --------------------------------------------------------
extern "C" void kernel_launch(void* const* d_in, const int* in_sizes, int n_in,
                              void* d_out, int out_size) {
    const float* x   = (const float*)d_in[0];
    const float* imp = (const float*)d_in[1];
    const float* Wc  = (const float*)d_in[2];
    const float* WQ  = (const float*)d_in[3];
    const float* WK  = (const float*)d_in[4];
    const float* WV  = (const float*)d_in[5];
    const float* Wm  = (const float*)d_in[6];
    const float* CN  = (const float*)d_in[7];
    const float* EP  = (const float*)d_in[8];
    const float* kK  = (const float*)d_in[9];
    const float* kV  = (const float*)d_in[10];
    const float* WO  = (const float*)d_in[11];
    const float* g1  = (const float*)d_in[12];
    const float* b1  = (const float*)d_in[13];
    const float* g2  = (const float*)d_in[14];
    const float* b2  = (const float*)d_in[15];
    float* out = (float*)d_out;

    float *nx, *nx2, *w, *wm, *sc, *mc, *h, *qm, *eq, *ek, *ev;
    float *q, *k, *v, *ao, *x1, *msb, *lgp;
    cudaGetSymbolAddress((void**)&nx,  g_nx);
    cudaGetSymbolAddress((void**)&nx2, g_nx2);
    cudaGetSymbolAddress((void**)&w,   g_w);
    cudaGetSymbolAddress((void**)&wm,  g_wm);
    cudaGetSymbolAddress((void**)&sc,  g_sc);
    cudaGetSymbolAddress((void**)&mc,  g_mc);
    cudaGetSymbolAddress((void**)&h,   g_h);
    cudaGetSymbolAddress((void**)&qm,  g_qm);
    cudaGetSymbolAddress((void**)&eq,  g_eq);
    cudaGetSymbolAddress((void**)&ek,  g_ek);
    cudaGetSymbolAddress((void**)&ev,  g_ev);
    cudaGetSymbolAddress((void**)&q,   g_q);
    cudaGetSymbolAddress((void**)&k,   g_k);
    cudaGetSymbolAddress((void**)&v,   g_v);
    cudaGetSymbolAddress((void**)&ao,  g_ao);
    cudaGetSymbolAddress((void**)&x1,  g_x1);
    cudaGetSymbolAddress((void**)&msb, g_ms);
    cudaGetSymbolAddress((void**)&lgp, g_lgp);

    const long SD = (long)SS * DD;
    const long DR = (long)DD * RR;
    const long SR = (long)SS * RR;
    const long SNK = (long)SS * NKK;

    // ---- attention sub-block ----
    ln_kernel<<<BB * SS, 256>>>(x, g1, b1, nx);
    zeroall_kernel<<<1024, 256>>>((float4*)h, (float4*)qm, (float4*)lgp, w, wm);
    route6_kernel<<<dim3(TT / 16, 4), 256>>>(nx, Wc, WQ, WK, WV, 64, lgp);
    pool4_kernel<<<TT / 4, 256>>>(lgp, imp, 4, w);
    norm_kernel<<<1, 32>>>(w, 4 * BB);
    mixfused2_kernel<<<2048, 256>>>(w, CN, EP, sc, eq, ek, ev);
    // h = nx @ sc : split-K x2, 128 CTAs
    splitk_kernel<<<dim3(RR / 128, SS / 128, 4), 256>>>(
        nx, sc, h, RR, DD / 2, DD, RR, SD, DR, SR);
    qkv_kernel<<<dim3(DD / 128, SS / 128, 6), 256>>>(h, eq, ek, ev, q, k, v);
    fattn_kernel<<<dim3(SS / 128, HH, BB), 256>>>(q, k, v, ao);
    // x1 = x + ao @ WO^T : fp16 NT
    hgemm_nt_kernel<true, false><<<dim3(DD / 128, (BB * SS) / 128, 1), 256>>>(
        ao, WO, x, x1, DD, DD, DD, DD, 1.f, 0, 0, 0, 0);

    // ---- memory sub-block ----
    ln_kernel<<<BB * SS, 256>>>(x1, g2, b2, nx2);
    route6_kernel<<<dim3(TT / 16, 4), 256>>>(nx2, Wm, Wm, Wm, Wm, 16, lgp);
    pool4_kernel<<<TT / 4, 256>>>(lgp, imp, 1, wm);
    norm_kernel<<<1, 32>>>(wm, BB);
    mix2_kernel<<<1024, 256>>>(wm, CN, mc);
    // Qm = nx2 @ mc : split-K x2
    splitk_kernel<<<dim3(RR / 128, SS / 128, 4), 256>>>(
        nx2, mc, qm, RR, DD / 2, DD, RR, SD, DR, SR);
    // ms = Qm @ kK^T / sqrt(256) : fp16 NT, fp16 out
    hgemm_nt_kernel<false, true><<<dim3(NKK / 128, SS / 128, BB), 256>>>(
        qm, kK, nullptr, msb, NKK, RR, RR, RR, 0.0625f, SR, 0, SNK, 0);
    topk4_kernel<<<BB * SS, 256>>>((const __half*)msb, x1, kV, out);
}

// round 12
// speedup vs baseline: 1.0098x; 1.0098x over previous
#include <cuda_runtime.h>
#include <cuda_bf16.h>
#include <cuda_fp16.h>
#include <math.h>
#include <stdint.h>

#define BB 2
#define SS 2048
#define DD 1024
#define HH 16
#define DHD 64
#define RR 256
#define NEXP 16
#define NKK 4096
#define TK 8
#define TT (BB*SS)

// ---------------- scratch (device globals; no allocation allowed) -------------
__device__ float g_nx [BB*SS*DD];
__device__ float g_nx2[BB*SS*DD];
__device__ float g_w  [4*BB*NEXP];
__device__ float g_wm [BB*NEXP];
__device__ float g_sc [BB*DD*RR];
__device__ float g_mc [BB*DD*RR];
__device__ float g_h  [BB*SS*RR];
__device__ float g_qm [BB*SS*RR];
__device__ float g_eq [BB*RR*DD];
__device__ float g_ek [BB*RR*DD];
__device__ float g_ev [BB*RR*DD];
__device__ float g_q  [BB*SS*DD];
__device__ float g_k  [BB*SS*DD];
__device__ float g_v  [BB*SS*DD];
__device__ float g_ao [BB*SS*DD];
__device__ float g_x1 [BB*SS*DD];
__device__ float g_ms [(size_t)BB*SS*NKK];   // used as fp16 (half capacity)
__device__ float g_lgp[(size_t)TT*64];       // compact pooled logits

// ---------------- utility ------------------------------------------------------
// zero h, qm (1M floats each), lgp (256K), w/wm. grid 1024 x 256.
__global__ void __launch_bounds__(256) zeroall_kernel(float4* h4, float4* q4,
                                                      float4* lgp4,
                                                      float* w, float* wm) {
    int i = blockIdx.x * 256 + threadIdx.x;
    float4 z = make_float4(0.f, 0.f, 0.f, 0.f);
    h4[i] = z; q4[i] = z;
    if (blockIdx.x < 256) lgp4[i] = z;
    if (blockIdx.x == 0) {
        if (threadIdx.x < 128) w[threadIdx.x] = 0.f;
        else if (threadIdx.x < 160) wm[threadIdx.x - 128] = 0.f;
    }
}

__device__ __forceinline__ float tf32r(float x) {
    uint32_t u;
    asm("cvt.rna.tf32.f32 %0, %1;" : "=r"(u) : "f"(x));
    return __uint_as_float(u);
}

__device__ __forceinline__ void sts4_tf32(float* p, float4 v) {
    float4 o;
    o.x = tf32r(v.x); o.y = tf32r(v.y); o.z = tf32r(v.z); o.w = tf32r(v.w);
    *(float4*)p = o;
}

__device__ __forceinline__ void mma8(float* c, const float* a, const float* b) {
    uint32_t A0 = __float_as_uint(a[0]), A1 = __float_as_uint(a[1]);
    uint32_t A2 = __float_as_uint(a[2]), A3 = __float_as_uint(a[3]);
    uint32_t B0 = __float_as_uint(b[0]), B1 = __float_as_uint(b[1]);
    asm volatile(
        "mma.sync.aligned.m16n8k8.row.col.f32.tf32.tf32.f32 "
        "{%0,%1,%2,%3}, {%4,%5,%6,%7}, {%8,%9}, {%0,%1,%2,%3};\n"
        : "+f"(c[0]), "+f"(c[1]), "+f"(c[2]), "+f"(c[3])
        : "r"(A0), "r"(A1), "r"(A2), "r"(A3), "r"(B0), "r"(B1));
}

__device__ __forceinline__ void mma16(float* c, const uint32_t* a, const uint32_t* b) {
    asm volatile(
        "mma.sync.aligned.m16n8k16.row.col.f32.f16.f16.f32 "
        "{%0,%1,%2,%3}, {%4,%5,%6,%7}, {%8,%9}, {%0,%1,%2,%3};\n"
        : "+f"(c[0]), "+f"(c[1]), "+f"(c[2]), "+f"(c[3])
        : "r"(a[0]), "r"(a[1]), "r"(a[2]), "r"(a[3]), "r"(b[0]), "r"(b[1]));
}

// ---------------- LayerNorm: one block per row, 256 threads --------------------
__global__ void __launch_bounds__(256) ln_kernel(const float* __restrict__ x,
                                                 const float* __restrict__ g,
                                                 const float* __restrict__ b,
                                                 float* __restrict__ out) {
    int row = blockIdx.x;
    const float4* xr = (const float4*)(x + (size_t)row * DD);
    float4 t = xr[threadIdx.x];
    float s  = t.x + t.y + t.z + t.w;
    float sq = t.x*t.x + t.y*t.y + t.z*t.z + t.w*t.w;
    __shared__ float rs[8], rq[8];
    for (int o = 16; o; o >>= 1) {
        s  += __shfl_down_sync(0xffffffffu, s,  o);
        sq += __shfl_down_sync(0xffffffffu, sq, o);
    }
    int wid = threadIdx.x >> 5, lane = threadIdx.x & 31;
    if (lane == 0) { rs[wid] = s; rq[wid] = sq; }
    __syncthreads();
    if (threadIdx.x == 0) {
        float a = 0.f, c = 0.f;
        for (int i = 0; i < 8; i++) { a += rs[i]; c += rq[i]; }
        rs[0] = a; rq[0] = c;
    }
    __syncthreads();
    float mean = rs[0] * (1.f / DD);
    float var  = rq[0] * (1.f / DD) - mean * mean;
    float rstd = rsqrtf(var + 1e-5f);
    float4 gg = ((const float4*)g)[threadIdx.x];
    float4 bb = ((const float4*)b)[threadIdx.x];
    float4 o4;
    o4.x = (t.x - mean) * rstd * gg.x + bb.x;
    o4.y = (t.y - mean) * rstd * gg.y + bb.y;
    o4.z = (t.z - mean) * rstd * gg.z + bb.z;
    o4.w = (t.w - mean) * rstd * gg.w + bb.w;
    ((float4*)(out + (size_t)row * DD))[threadIdx.x] = o4;
}

// ---------------- routing v6: 4 tok x 4 exp, 2 chunks/block, atomic pool -------
// grid (TT/16, 4). Block accumulates chunks y and y+4, atomicAdds into compact
// lgp[token][64] (pre-zeroed; pool4 clears after read for next pass/replay).
__global__ void __launch_bounds__(256) route6_kernel(
    const float* __restrict__ nx,
    const float* __restrict__ W0, const float* __restrict__ W1,
    const float* __restrict__ W2, const float* __restrict__ W3,
    int nE, float* __restrict__ lgp) {
    __shared__ float xs[16 * 132];
    __shared__ float ws[64 * 132];   // reused as partials [4][16][68]
    int tid = threadIdx.x;
    int tok0 = blockIdx.x * 16;
    int dq = tid >> 6, tg = (tid >> 4) & 3, eg = tid & 15;
    const float* Ws[4] = {W0, W1, W2, W3};
    bool em[4];
#pragma unroll
    for (int i = 0; i < 4; i++) em[i] = (eg + i * 16) < nE;
    float a[4][4];
#pragma unroll
    for (int j = 0; j < 4; j++)
#pragma unroll
        for (int i = 0; i < 4; i++) a[j][i] = 0.f;

#pragma unroll
    for (int ci = 0; ci < 2; ci++) {
        int c = blockIdx.y + ci * 4;
        __syncthreads();
#pragma unroll
        for (int i = 0; i < 2; i++) {
            int f = tid + 256 * i;
            int tt = f >> 5, d4 = f & 31;
            *(float4*)&xs[tt * 132 + d4 * 4] =
                *(const float4*)(nx + (size_t)(tok0 + tt) * DD + c * 128 + d4 * 4);
        }
#pragma unroll
        for (int i = 0; i < 8; i++) {
            int f = tid + 256 * i;
            if (f < nE * 32) {
                int e = f >> 5, d4 = f & 31;
                const float* src = Ws[e >> 4] + (size_t)(e & 15) * DD + c * 128 + d4 * 4;
                *(float4*)&ws[e * 132 + d4 * 4] = *(const float4*)src;
            }
        }
        __syncthreads();
#pragma unroll
        for (int d4 = dq * 8; d4 < dq * 8 + 8; d4++) {
            float4 xv[4], wv[4];
#pragma unroll
            for (int j = 0; j < 4; j++)
                xv[j] = *(float4*)&xs[(tg * 4 + j) * 132 + d4 * 4];
#pragma unroll
            for (int i = 0; i < 4; i++)
                wv[i] = em[i] ? *(float4*)&ws[(eg + i * 16) * 132 + d4 * 4]
                              : make_float4(0.f, 0.f, 0.f, 0.f);
#pragma unroll
            for (int j = 0; j < 4; j++)
#pragma unroll
                for (int i = 0; i < 4; i++)
                    a[j][i] += xv[j].x * wv[i].x + xv[j].y * wv[i].y +
                               xv[j].z * wv[i].z + xv[j].w * wv[i].w;
        }
    }
    __syncthreads();
    float* part = ws;     // [dq][t(16)][68]
#pragma unroll
    for (int j = 0; j < 4; j++)
#pragma unroll
        for (int i = 0; i < 4; i++)
            part[dq * 1088 + (tg * 4 + j) * 68 + eg + i * 16] = a[j][i];
    __syncthreads();
    {
        int t = tid >> 4, e0 = (tid * 4) & 63;
        float4 s = make_float4(0.f, 0.f, 0.f, 0.f);
#pragma unroll
        for (int d = 0; d < 4; d++) {
            float4 p = *(float4*)&part[d * 1088 + t * 68 + e0];
            s.x += p.x; s.y += p.y; s.z += p.z; s.w += p.w;
        }
        float* dst = &lgp[(size_t)(tok0 + t) * 64 + e0];
        atomicAdd(dst + 0, s.x);
        atomicAdd(dst + 1, s.y);
        atomicAdd(dst + 2, s.z);
        atomicAdd(dst + 3, s.w);
    }
}

// pool compact logits: softmax in 16-expert segments, pooled accumulate.
// Clears lgp after reading (ready for next routing pass / graph replay).
__global__ void __launch_bounds__(256) pool4_kernel(
    float* __restrict__ lgp, const float* __restrict__ imp,
    int nW, float* __restrict__ wacc) {
    int tid = threadIdx.x;
    int t = tid >> 6, e = tid & 63;
    int tok = blockIdx.x * 4 + t;
    size_t idx = (size_t)tok * 64 + e;
    float l = lgp[idx];
    lgp[idx] = 0.f;
    float mx = l;
#pragma unroll
    for (int o = 1; o < 16; o <<= 1)
        mx = fmaxf(mx, __shfl_xor_sync(0xffffffffu, mx, o));
    float ev = __expf(l - mx);
    float s = ev;
#pragma unroll
    for (int o = 1; o < 16; o <<= 1)
        s += __shfl_xor_sync(0xffffffffu, s, o);
    if (e < nW * NEXP) {
        int r = e >> 4, n = e & 15, b = tok / SS;
        atomicAdd(&wacc[(r * BB + b) * NEXP + n], imp[tok] * ev / s);
    }
}

__global__ void norm_kernel(float* w, int cnt) {
    int i = threadIdx.x;
    if (i < cnt) {
        float* p = w + i * NEXP;
        float s = 0.f;
        for (int n = 0; n < NEXP; n++) s += p[n];
        float inv = 1.f / (s + 1e-8f);
        for (int n = 0; n < NEXP; n++) p[n] *= inv;
    }
}

// ---------------- pool mixes: both batches per thread (pool read once) ---------
__global__ void __launch_bounds__(256) mixfused2_kernel(
    const float* __restrict__ w, const float* __restrict__ CN,
    const float* __restrict__ EP, float* __restrict__ sc,
    float* __restrict__ eq, float* __restrict__ ek, float* __restrict__ ev) {
    const size_t X = (size_t)DD * RR;
    if (blockIdx.x < 1024) {
        size_t r = (size_t)blockIdx.x * 256 + threadIdx.x;
        float a0 = 0.f, a1 = 0.f;
#pragma unroll
        for (int n = 0; n < NEXP; n++) {
            float p = CN[(size_t)n * X + r];
            a0 += w[n] * p;
            a1 += w[16 + n] * p;
        }
        sc[r] = a0; sc[X + r] = a1;
    } else {
        size_t r = (size_t)(blockIdx.x - 1024) * 256 + threadIdx.x;
        float q0 = 0.f, q1 = 0.f, k0 = 0.f, k1 = 0.f, v0 = 0.f, v1 = 0.f;
#pragma unroll
        for (int n = 0; n < NEXP; n++) {
            float p = EP[(size_t)n * X + r];
            q0 += w[32 + n] * p; q1 += w[48 + n] * p;
            k0 += w[64 + n] * p; k1 += w[80 + n] * p;
            v0 += w[96 + n] * p; v1 += w[112 + n] * p;
        }
        eq[r] = q0; eq[X + r] = q1;
        ek[r] = k0; ek[X + r] = k1;
        ev[r] = v0; ev[X + r] = v1;
    }
}

__global__ void __launch_bounds__(256) mix2_kernel(
    const float* __restrict__ wm, const float* __restrict__ CN,
    float* __restrict__ mc) {
    const size_t X = (size_t)DD * RR;
    size_t r = (size_t)blockIdx.x * 256 + threadIdx.x;
    float a0 = 0.f, a1 = 0.f;
#pragma unroll
    for (int n = 0; n < NEXP; n++) {
        float p = CN[(size_t)n * X + r];
        a0 += wm[n] * p;
        a1 += wm[16 + n] * p;
    }
    mc[r] = a0; mc[X + r] = a1;
}

// ---------------- tf32 tensor-core GEMM body (NN path) -------------------------
template<bool TRANSB, bool RES, bool ATOM>
__device__ __forceinline__ void tgemm_body(
    const float* __restrict__ A, const float* __restrict__ B,
    const float* __restrict__ resp, float* __restrict__ Cf,
    int N, int K, int lda, int ldb, float alpha) {
    const int n0 = blockIdx.x * 128, m0 = blockIdx.y * 128;
    __shared__ float As[128 * 20];
    __shared__ float Bs[2560];
    int tid = threadIdx.x;
    int lane = tid & 31, w = tid >> 5;
    int wm = (w & 1) * 64, wn = (w >> 1) * 32;
    int lq = lane >> 2, lr = lane & 3;

    int rowA = tid >> 2, c4A = (tid & 3) * 4;
    const float* gA = A + (size_t)(m0 + rowA) * lda + c4A;
    float* sAp = &As[rowA * 20 + c4A];
    const float* gB;
    float* sBp;
    int gBstep, gBoff2, sBoff2;
    if (!TRANSB) {
        int rB = tid >> 5, cB = (tid & 31) * 4;
        gB = B + (size_t)rB * ldb + n0 + cB;
        sBp = &Bs[rB * 136 + cB];
        gBstep = 16 * ldb; gBoff2 = 8 * ldb; sBoff2 = 8 * 136;
    } else {
        int nB = tid >> 2, c4B = (tid & 3) * 4;
        gB = B + (size_t)(n0 + nB) * ldb + c4B;
        sBp = &Bs[nB * 20 + c4B];
        gBstep = 16; gBoff2 = 64 * ldb; sBoff2 = 64 * 20;
    }

    float acc[4][4][4];
#pragma unroll
    for (int mt = 0; mt < 4; mt++)
#pragma unroll
        for (int nt = 0; nt < 4; nt++)
#pragma unroll
            for (int i = 0; i < 4; i++) acc[mt][nt][i] = 0.f;

    float4 pa0 = *(const float4*)gA;
    float4 pa1 = *(const float4*)(gA + (size_t)64 * lda);
    float4 pb0 = *(const float4*)gB;
    float4 pb1 = *(const float4*)(gB + gBoff2);

    for (int kt = 0; kt < K; kt += 16) {
        sts4_tf32(sAp, pa0);
        sts4_tf32(sAp + 64 * 20, pa1);
        sts4_tf32(sBp, pb0);
        sts4_tf32(sBp + sBoff2, pb1);
        __syncthreads();
        if (kt + 16 < K) {
            gA += 16;
            pa0 = *(const float4*)gA;
            pa1 = *(const float4*)(gA + (size_t)64 * lda);
            gB += gBstep;
            pb0 = *(const float4*)gB;
            pb1 = *(const float4*)(gB + gBoff2);
        }
#pragma unroll
        for (int ks = 0; ks < 16; ks += 8) {
            float af[4][4], bf[4][2];
#pragma unroll
            for (int mt = 0; mt < 4; mt++) {
                int r = wm + mt * 16 + lq;
                af[mt][0] = As[r * 20 + ks + lr];
                af[mt][1] = As[(r + 8) * 20 + ks + lr];
                af[mt][2] = As[r * 20 + ks + lr + 4];
                af[mt][3] = As[(r + 8) * 20 + ks + lr + 4];
            }
#pragma unroll
            for (int nt = 0; nt < 4; nt++) {
                int cc = wn + nt * 8 + lq;
                if (!TRANSB) {
                    bf[nt][0] = Bs[(ks + lr) * 136 + cc];
                    bf[nt][1] = Bs[(ks + 4 + lr) * 136 + cc];
                } else {
                    bf[nt][0] = Bs[cc * 20 + ks + lr];
                    bf[nt][1] = Bs[cc * 20 + ks + 4 + lr];
                }
            }
#pragma unroll
            for (int mt = 0; mt < 4; mt++)
#pragma unroll
                for (int nt = 0; nt < 4; nt++)
                    mma8(acc[mt][nt], af[mt], bf[nt]);
        }
        __syncthreads();
    }
#pragma unroll
    for (int mt = 0; mt < 4; mt++) {
        int r = m0 + wm + mt * 16 + lq;
#pragma unroll
        for (int nt = 0; nt < 4; nt++) {
            int cc = n0 + wn + nt * 8 + 2 * lr;
            float2 v0 = make_float2(alpha * acc[mt][nt][0], alpha * acc[mt][nt][1]);
            float2 v1 = make_float2(alpha * acc[mt][nt][2], alpha * acc[mt][nt][3]);
            size_t o0 = (size_t)r * N + cc;
            size_t o1 = (size_t)(r + 8) * N + cc;
            if (ATOM) {
                atomicAdd(Cf + o0, v0.x); atomicAdd(Cf + o0 + 1, v0.y);
                atomicAdd(Cf + o1, v1.x); atomicAdd(Cf + o1 + 1, v1.y);
            } else {
                if (RES) {
                    float2 r0 = *(const float2*)(resp + o0);
                    float2 r1 = *(const float2*)(resp + o1);
                    v0.x += r0.x; v0.y += r0.y;
                    v1.x += r1.x; v1.y += r1.y;
                }
                *(float2*)(Cf + o0) = v0;
                *(float2*)(Cf + o1) = v1;
            }
        }
    }
}

// split-K (x2) NN GEMM with atomic epilogue. grid.z = b*2 + ks.
__global__ void __launch_bounds__(256, 2) splitk_kernel(
    const float* __restrict__ A, const float* __restrict__ B,
    float* __restrict__ C, int N, int Kh, int lda, int ldb,
    long sA, long sB, long sC) {
    int z = blockIdx.z;
    int b = z >> 1, ks = z & 1;
    A += (size_t)b * sA + (size_t)ks * Kh;
    B += (size_t)b * sB + (size_t)ks * Kh * ldb;
    C += (size_t)b * sC;
    tgemm_body<false, false, true>(A, B, nullptr, C, N, Kh, lda, ldb, 1.f);
}

// merged Q/K/V projection: grid.z = 6 (which = z>>1, b = z&1)
__global__ void __launch_bounds__(256, 2) qkv_kernel(
    const float* __restrict__ h,
    const float* __restrict__ eq, const float* __restrict__ ek,
    const float* __restrict__ ev,
    float* __restrict__ q, float* __restrict__ k, float* __restrict__ v) {
    int z = blockIdx.z;
    int b = z & 1, which = z >> 1;
    const float* B = (which == 0 ? eq : which == 1 ? ek : ev) + (size_t)b * RR * DD;
    float* C = (which == 0 ? q : which == 1 ? k : v) + (size_t)b * SS * DD;
    const float* A = h + (size_t)b * SS * RR;
    tgemm_body<false, false, false>(A, B, nullptr, C, DD, RR, RR, DD, 1.f);
}

// ---------------- fp16 m16n8k16 NT GEMM: 128x128 tile, BK=32 -------------------
// A [M,K] fp32, B [N,K] fp32 (both k-contiguous), converted to fp16 at staging.
// fp16 eps == tf32 eps (10-bit mantissa) -> accuracy-neutral vs tf32.
template<bool RES, bool OUTHALF>
__global__ void __launch_bounds__(256, 2) hgemm_nt_kernel(
    const float* __restrict__ A, const float* __restrict__ B,
    const float* __restrict__ resp, void* __restrict__ Cv,
    int N, int K, int lda, int ldb, float alpha,
    long sA, long sB, long sC, long sR) {
    A += (size_t)blockIdx.z * sA;
    B += (size_t)blockIdx.z * sB;
    __half* Ch = (__half*)Cv;
    float* Cf = (float*)Cv;
    if (OUTHALF) Ch += (size_t)blockIdx.z * sC;
    else         Cf += (size_t)blockIdx.z * sC;
    if (RES) resp += (size_t)blockIdx.z * sR;
    const int n0 = blockIdx.x * 128, m0 = blockIdx.y * 128;
    __shared__ uint32_t AsW[128 * 20];   // [row][k-pairs], 16 data + 4 pad words
    __shared__ uint32_t BsW[128 * 20];
    int tid = threadIdx.x, lane = tid & 31, w = tid >> 5;
    int wm = (w & 1) * 64, wn = (w >> 1) * 32;
    int lq = lane >> 2, lr = lane & 3;
    int row = tid >> 3, c4 = tid & 7;    // row 0-31, float4 index within 32 k-vals

    const float* gA = A + (size_t)(m0 + row) * lda + c4 * 4;
    const float* gB = B + (size_t)(n0 + row) * ldb + c4 * 4;
    float4 pa[4], pb[4];
#pragma unroll
    for (int i = 0; i < 4; i++) {
        pa[i] = *(const float4*)(gA + (size_t)(32 * i) * lda);
        pb[i] = *(const float4*)(gB + (size_t)(32 * i) * ldb);
    }

    float acc[4][4][4];
#pragma unroll
    for (int mt = 0; mt < 4; mt++)
#pragma unroll
        for (int nt = 0; nt < 4; nt++)
#pragma unroll
            for (int i = 0; i < 4; i++) acc[mt][nt][i] = 0.f;

    for (int kt = 0; kt < K; kt += 32) {
#pragma unroll
        for (int i = 0; i < 4; i++) {
            __half2 h0 = __floats2half2_rn(pa[i].x, pa[i].y);
            __half2 h1 = __floats2half2_rn(pa[i].z, pa[i].w);
            uint2 ua;
            ua.x = *(uint32_t*)&h0; ua.y = *(uint32_t*)&h1;
            *(uint2*)&AsW[(row + 32 * i) * 20 + c4 * 2] = ua;
            __half2 g0 = __floats2half2_rn(pb[i].x, pb[i].y);
            __half2 g1 = __floats2half2_rn(pb[i].z, pb[i].w);
            uint2 ub;
            ub.x = *(uint32_t*)&g0; ub.y = *(uint32_t*)&g1;
            *(uint2*)&BsW[(row + 32 * i) * 20 + c4 * 2] = ub;
        }
        __syncthreads();
        if (kt + 32 < K) {
            gA += 32; gB += 32;
#pragma unroll
            for (int i = 0; i < 4; i++) {
                pa[i] = *(const float4*)(gA + (size_t)(32 * i) * lda);
                pb[i] = *(const float4*)(gB + (size_t)(32 * i) * ldb);
            }
        }
#pragma unroll
        for (int ks = 0; ks < 2; ks++) {
            uint32_t af[4][4], bf[4][2];
#pragma unroll
            for (int mt = 0; mt < 4; mt++) {
                int r = wm + mt * 16 + lq;
                af[mt][0] = AsW[r * 20 + ks * 8 + lr];
                af[mt][1] = AsW[(r + 8) * 20 + ks * 8 + lr];
                af[mt][2] = AsW[r * 20 + ks * 8 + 4 + lr];
                af[mt][3] = AsW[(r + 8) * 20 + ks * 8 + 4 + lr];
            }
#pragma unroll
            for (int nt = 0; nt < 4; nt++) {
                int cc = wn + nt * 8 + lq;
                bf[nt][0] = BsW[cc * 20 + ks * 8 + lr];
                bf[nt][1] = BsW[cc * 20 + ks * 8 + 4 + lr];
            }
#pragma unroll
            for (int mt = 0; mt < 4; mt++)
#pragma unroll
                for (int nt = 0; nt < 4; nt++)
                    mma16(acc[mt][nt], af[mt], bf[nt]);
        }
        __syncthreads();
    }
#pragma unroll
    for (int mt = 0; mt < 4; mt++) {
        int r = m0 + wm + mt * 16 + lq;
#pragma unroll
        for (int nt = 0; nt < 4; nt++) {
            int cc = n0 + wn + nt * 8 + 2 * lr;
            float2 v0 = make_float2(alpha * acc[mt][nt][0], alpha * acc[mt][nt][1]);
            float2 v1 = make_float2(alpha * acc[mt][nt][2], alpha * acc[mt][nt][3]);
            size_t o0 = (size_t)r * N + cc;
            size_t o1 = (size_t)(r + 8) * N + cc;
            if (OUTHALF) {
                *(__half2*)(Ch + o0) = __floats2half2_rn(v0.x, v0.y);
                *(__half2*)(Ch + o1) = __floats2half2_rn(v1.x, v1.y);
            } else {
                if (RES) {
                    float2 r0 = *(const float2*)(resp + o0);
                    float2 r1 = *(const float2*)(resp + o1);
                    v0.x += r0.x; v0.y += r0.y;
                    v1.x += r1.x; v1.y += r1.y;
                }
                *(float2*)(Cf + o0) = v0;
                *(float2*)(Cf + o1) = v1;
            }
        }
    }
}

// ---------------- tf32 tensor-core causal flash attention ----------------------
__global__ void __launch_bounds__(256, 2) fattn_kernel(
    const float* __restrict__ Q, const float* __restrict__ K,
    const float* __restrict__ V, float* __restrict__ O) {
    int b = blockIdx.z, h = blockIdx.y;
    int q0 = (gridDim.x - 1 - blockIdx.x) * 128;
    __shared__ float Ks[64 * 68];
    __shared__ float Vs[64 * 72];
    int tid = threadIdx.x, lane = tid & 31, w = tid >> 5;
    int lq = lane >> 2, lr = lane & 3;
    int wrow = q0 + w * 16;

    float qf[8][4];
    const float* Qb = Q + ((size_t)(b * SS + wrow)) * DD + h * DHD;
#pragma unroll
    for (int ks = 0; ks < 8; ks++) {
        qf[ks][0] = tf32r(0.125f * Qb[lq * DD + ks * 8 + lr]);
        qf[ks][1] = tf32r(0.125f * Qb[(lq + 8) * DD + ks * 8 + lr]);
        qf[ks][2] = tf32r(0.125f * Qb[lq * DD + ks * 8 + lr + 4]);
        qf[ks][3] = tf32r(0.125f * Qb[(lq + 8) * DD + ks * 8 + lr + 4]);
    }
    float of[8][4];
#pragma unroll
    for (int dt = 0; dt < 8; dt++) {
        of[dt][0] = 0.f; of[dt][1] = 0.f; of[dt][2] = 0.f; of[dt][3] = 0.f;
    }
    float m0 = -1e30f, m1 = -1e30f, l0 = 0.f, l1 = 0.f;

    int ntiles = q0 / 64 + 2;
    for (int ti = 0; ti < ntiles; ti++) {
        int j0 = ti * 64;
        __syncthreads();
#pragma unroll
        for (int i = 0; i < 4; i++) {
            int f = tid + 256 * i;
            int r = f >> 4, c4 = (f & 15) * 4;
            size_t goff = ((size_t)(b * SS + j0 + r)) * DD + h * DHD + c4;
            sts4_tf32(&Ks[r * 68 + c4], *(const float4*)(K + goff));
            sts4_tf32(&Vs[r * 72 + c4], *(const float4*)(V + goff));
        }
        __syncthreads();
        if (j0 > wrow + 15) continue;

        float sc[8][4];
#pragma unroll
        for (int nt = 0; nt < 8; nt++) {
            sc[nt][0] = 0.f; sc[nt][1] = 0.f; sc[nt][2] = 0.f; sc[nt][3] = 0.f;
        }
#pragma unroll
        for (int nt = 0; nt < 8; nt++)
#pragma unroll
            for (int ks = 0; ks < 8; ks++) {
                float bf[2];
                bf[0] = Ks[(nt * 8 + lq) * 68 + ks * 8 + lr];
                bf[1] = Ks[(nt * 8 + lq) * 68 + ks * 8 + lr + 4];
                mma8(sc[nt], qf[ks], bf);
            }
        if (j0 + 63 > wrow) {
            int r0 = wrow + lq, r1 = r0 + 8;
#pragma unroll
            for (int nt = 0; nt < 8; nt++) {
                int col = j0 + nt * 8 + 2 * lr;
                if (col > r0)     sc[nt][0] = -1e30f;
                if (col + 1 > r0) sc[nt][1] = -1e30f;
                if (col > r1)     sc[nt][2] = -1e30f;
                if (col + 1 > r1) sc[nt][3] = -1e30f;
            }
        }
        float mx0 = -1e30f, mx1 = -1e30f;
#pragma unroll
        for (int nt = 0; nt < 8; nt++) {
            mx0 = fmaxf(mx0, fmaxf(sc[nt][0], sc[nt][1]));
            mx1 = fmaxf(mx1, fmaxf(sc[nt][2], sc[nt][3]));
        }
        mx0 = fmaxf(mx0, __shfl_xor_sync(0xffffffffu, mx0, 1));
        mx0 = fmaxf(mx0, __shfl_xor_sync(0xffffffffu, mx0, 2));
        mx1 = fmaxf(mx1, __shfl_xor_sync(0xffffffffu, mx1, 1));
        mx1 = fmaxf(mx1, __shfl_xor_sync(0xffffffffu, mx1, 2));
        float mn0 = fmaxf(m0, mx0), mn1 = fmaxf(m1, mx1);
        float f0 = __expf(m0 - mn0), f1 = __expf(m1 - mn1);
        m0 = mn0; m1 = mn1;
        l0 *= f0; l1 *= f1;
#pragma unroll
        for (int dt = 0; dt < 8; dt++) {
            of[dt][0] *= f0; of[dt][1] *= f0;
            of[dt][2] *= f1; of[dt][3] *= f1;
        }
        float rs0 = 0.f, rs1 = 0.f;
#pragma unroll
        for (int nt = 0; nt < 8; nt++) {
            float p0 = tf32r(__expf(sc[nt][0] - m0));
            float p1 = tf32r(__expf(sc[nt][1] - m0));
            float p2 = tf32r(__expf(sc[nt][2] - m1));
            float p3 = tf32r(__expf(sc[nt][3] - m1));
            sc[nt][0] = p0; sc[nt][1] = p1; sc[nt][2] = p2; sc[nt][3] = p3;
            rs0 += p0 + p1; rs1 += p2 + p3;
        }
        rs0 += __shfl_xor_sync(0xffffffffu, rs0, 1);
        rs0 += __shfl_xor_sync(0xffffffffu, rs0, 2);
        rs1 += __shfl_xor_sync(0xffffffffu, rs1, 1);
        rs1 += __shfl_xor_sync(0xffffffffu, rs1, 2);
        l0 += rs0; l1 += rs1;
        int srcA = (lane & ~3) | (lr >> 1);
        int srcB = srcA | 2;
        bool odd = (lr & 1) != 0;
#pragma unroll
        for (int nt = 0; nt < 8; nt++) {
            float t00 = __shfl_sync(0xffffffffu, sc[nt][0], srcA);
            float t01 = __shfl_sync(0xffffffffu, sc[nt][1], srcA);
            float t02 = __shfl_sync(0xffffffffu, sc[nt][2], srcA);
            float t03 = __shfl_sync(0xffffffffu, sc[nt][3], srcA);
            float u00 = __shfl_sync(0xffffffffu, sc[nt][0], srcB);
            float u01 = __shfl_sync(0xffffffffu, sc[nt][1], srcB);
            float u02 = __shfl_sync(0xffffffffu, sc[nt][2], srcB);
            float u03 = __shfl_sync(0xffffffffu, sc[nt][3], srcB);
            float pa[4];
            pa[0] = odd ? t01 : t00;
            pa[1] = odd ? t03 : t02;
            pa[2] = odd ? u01 : u00;
            pa[3] = odd ? u03 : u02;
#pragma unroll
            for (int dt = 0; dt < 8; dt++) {
                float bf[2];
                bf[0] = Vs[(nt * 8 + lr) * 72 + dt * 8 + lq];
                bf[1] = Vs[(nt * 8 + lr + 4) * 72 + dt * 8 + lq];
                mma8(of[dt], pa, bf);
            }
        }
    }
    float inv0 = 1.f / l0, inv1 = 1.f / l1;
    float* Ob0 = O + ((size_t)(b * SS + wrow + lq)) * DD + h * DHD;
    float* Ob1 = Ob0 + (size_t)8 * DD;
#pragma unroll
    for (int dt = 0; dt < 8; dt++) {
        *(float2*)&Ob0[dt * 8 + 2 * lr] = make_float2(of[dt][0] * inv0, of[dt][1] * inv0);
        *(float2*)&Ob1[dt * 8 + 2 * lr] = make_float2(of[dt][2] * inv1, of[dt][3] * inv1);
    }
}

// ---------------- top-8 over fp16 scores + gather + residual -------------------
__global__ void __launch_bounds__(256) topk4_kernel(const __half* __restrict__ ms,
                                                    const float* __restrict__ x1,
                                                    const float* __restrict__ KV,
                                                    float* __restrict__ out) {
    int token = blockIdx.x;
    int tid = threadIdx.x, w = tid >> 5, lane = tid & 31;
    const __half* row = ms + (size_t)token * NKK;
    float r[16];
#pragma unroll
    for (int i = 0; i < 4; i++) {
        uint2 u = *(const uint2*)(row + w * 512 + i * 128 + lane * 4);
        float2 f01 = __half22float2(*(const __half2*)&u.x);
        float2 f23 = __half22float2(*(const __half2*)&u.y);
        r[i * 4 + 0] = f01.x; r[i * 4 + 1] = f01.y;
        r[i * 4 + 2] = f23.x; r[i * 4 + 3] = f23.y;
    }
    __shared__ float cv_s[64];
    __shared__ int   ci_s[64];
    __shared__ float tv[TK];
    __shared__ int   tix[TK];
    __shared__ float w8[TK];
    uint32_t taken = 0;
    for (int k = 0; k < TK; k++) {
        float bv = -1e30f; int bi = 0;
#pragma unroll
        for (int i = 0; i < 16; i++) {
            if (!((taken >> i) & 1u) && r[i] > bv) { bv = r[i]; bi = i; }
        }
        int mygi = w * 512 + (bi >> 2) * 128 + lane * 4 + (bi & 3);
        float rv = bv; int gi = mygi;
#pragma unroll
        for (int o = 16; o; o >>= 1) {
            float ov = __shfl_xor_sync(0xffffffffu, rv, o);
            int   oi = __shfl_xor_sync(0xffffffffu, gi, o);
            if (ov > rv || (ov == rv && oi < gi)) { rv = ov; gi = oi; }
        }
        if (gi == mygi) taken |= 1u << bi;
        if (lane == 0) { cv_s[w * 8 + k] = rv; ci_s[w * 8 + k] = gi; }
    }
    __syncthreads();
    if (w == 0) {
        float c0 = cv_s[lane], c1 = cv_s[lane + 32];
        int i0 = ci_s[lane], i1 = ci_s[lane + 32];
        uint32_t tk = 0;
        for (int k = 0; k < TK; k++) {
            float bv = -1e30f; int gi = 0x7fffffff; int sel = -1;
            if (!(tk & 1u)) { bv = c0; gi = i0; sel = 0; }
            if (!(tk & 2u) && (c1 > bv || (c1 == bv && i1 < gi))) {
                bv = c1; gi = i1; sel = 1;
            }
            float rv = bv; int g = gi;
#pragma unroll
            for (int o = 16; o; o >>= 1) {
                float ov = __shfl_xor_sync(0xffffffffu, rv, o);
                int   oi = __shfl_xor_sync(0xffffffffu, g, o);
                if (ov > rv || (ov == rv && oi < g)) { rv = ov; g = oi; }
            }
            if (sel >= 0 && g == gi) tk |= (sel ? 2u : 1u);
            if (lane == 0) { tv[k] = rv; tix[k] = g; }
        }
        if (lane == 0) {
            float mx = tv[0];
            float e[TK], s = 0.f;
            for (int k = 0; k < TK; k++) { e[k] = __expf(tv[k] - mx); s += e[k]; }
            float inv = 1.f / s;
            for (int k = 0; k < TK; k++) w8[k] = e[k] * inv;
        }
    }
    __syncthreads();
    {
        float4 acc = *(const float4*)(x1 + (size_t)token * DD + tid * 4);
#pragma unroll
        for (int k = 0; k < TK; k++) {
            float4 kv = *(const float4*)(KV + (size_t)tix[k] * DD + tid * 4);
            float wk = w8[k];
            acc.x += wk * kv.x; acc.y += wk * kv.y;
            acc.z += wk * kv.z; acc.w += wk * kv.w;
        }
        *(float4*)(out + (size_t)token * DD + tid * 4) = acc;
    }
}

// ---------------- driver --------------------------------------------------------
extern "C" void kernel_launch(void* const* d_in, const int* in_sizes, int n_in,
                              void* d_out, int out_size) {
    const float* x   = (const float*)d_in[0];
    const float* imp = (const float*)d_in[1];
    const float* Wc  = (const float*)d_in[2];
    const float* WQ  = (const float*)d_in[3];
    const float* WK  = (const float*)d_in[4];
    const float* WV  = (const float*)d_in[5];
    const float* Wm  = (const float*)d_in[6];
    const float* CN  = (const float*)d_in[7];
    const float* EP  = (const float*)d_in[8];
    const float* kK  = (const float*)d_in[9];
    const float* kV  = (const float*)d_in[10];
    const float* WO  = (const float*)d_in[11];
    const float* g1  = (const float*)d_in[12];
    const float* b1  = (const float*)d_in[13];
    const float* g2  = (const float*)d_in[14];
    const float* b2  = (const float*)d_in[15];
    float* out = (float*)d_out;

    float *nx, *nx2, *w, *wm, *sc, *mc, *h, *qm, *eq, *ek, *ev;
    float *q, *k, *v, *ao, *x1, *msb, *lgp;
    cudaGetSymbolAddress((void**)&nx,  g_nx);
    cudaGetSymbolAddress((void**)&nx2, g_nx2);
    cudaGetSymbolAddress((void**)&w,   g_w);
    cudaGetSymbolAddress((void**)&wm,  g_wm);
    cudaGetSymbolAddress((void**)&sc,  g_sc);
    cudaGetSymbolAddress((void**)&mc,  g_mc);
    cudaGetSymbolAddress((void**)&h,   g_h);
    cudaGetSymbolAddress((void**)&qm,  g_qm);
    cudaGetSymbolAddress((void**)&eq,  g_eq);
    cudaGetSymbolAddress((void**)&ek,  g_ek);
    cudaGetSymbolAddress((void**)&ev,  g_ev);
    cudaGetSymbolAddress((void**)&q,   g_q);
    cudaGetSymbolAddress((void**)&k,   g_k);
    cudaGetSymbolAddress((void**)&v,   g_v);
    cudaGetSymbolAddress((void**)&ao,  g_ao);
    cudaGetSymbolAddress((void**)&x1,  g_x1);
    cudaGetSymbolAddress((void**)&msb, g_ms);
    cudaGetSymbolAddress((void**)&lgp, g_lgp);

    const long SD = (long)SS * DD;
    const long DR = (long)DD * RR;
    const long SR = (long)SS * RR;
    const long SNK = (long)SS * NKK;

    // ---- attention sub-block ----
    ln_kernel<<<BB * SS, 256>>>(x, g1, b1, nx);
    zeroall_kernel<<<1024, 256>>>((float4*)h, (float4*)qm, (float4*)lgp, w, wm);
    route6_kernel<<<dim3(TT / 16, 4), 256>>>(nx, Wc, WQ, WK, WV, 64, lgp);
    pool4_kernel<<<TT / 4, 256>>>(lgp, imp, 4, w);
    norm_kernel<<<1, 32>>>(w, 4 * BB);
    mixfused2_kernel<<<2048, 256>>>(w, CN, EP, sc, eq, ek, ev);
    // h = nx @ sc : split-K x2, 128 CTAs
    splitk_kernel<<<dim3(RR / 128, SS / 128, 4), 256>>>(
        nx, sc, h, RR, DD / 2, DD, RR, SD, DR, SR);
    qkv_kernel<<<dim3(DD / 128, SS / 128, 6), 256>>>(h, eq, ek, ev, q, k, v);
    fattn_kernel<<<dim3(SS / 128, HH, BB), 256>>>(q, k, v, ao);
    // x1 = x + ao @ WO^T : fp16 NT
    hgemm_nt_kernel<true, false><<<dim3(DD / 128, (BB * SS) / 128, 1), 256>>>(
        ao, WO, x, x1, DD, DD, DD, DD, 1.f, 0, 0, 0, 0);

    // ---- memory sub-block ----
    ln_kernel<<<BB * SS, 256>>>(x1, g2, b2, nx2);
    route6_kernel<<<dim3(TT / 16, 4), 256>>>(nx2, Wm, Wm, Wm, Wm, 16, lgp);
    pool4_kernel<<<TT / 4, 256>>>(lgp, imp, 1, wm);
    norm_kernel<<<1, 32>>>(wm, BB);
    mix2_kernel<<<1024, 256>>>(wm, CN, mc);
    // Qm = nx2 @ mc : split-K x2
    splitk_kernel<<<dim3(RR / 128, SS / 128, 4), 256>>>(
        nx2, mc, qm, RR, DD / 2, DD, RR, SD, DR, SR);
    // ms = Qm @ kK^T / sqrt(256) : fp16 NT, fp16 out
    hgemm_nt_kernel<false, true><<<dim3(NKK / 128, SS / 128, BB), 256>>>(
        qm, kK, nullptr, msb, NKK, RR, RR, RR, 0.0625f, SR, 0, SNK, 0);
    topk4_kernel<<<BB * SS, 256>>>((const __half*)msb, x1, kV, out);
}